// round 7
// baseline (speedup 1.0000x reference)
#include <cuda_runtime.h>
#include <cuda_fp16.h>
#include <cstdint>

// Problem dims
#define B_  8
#define LQ_ 512
#define LK_ 512
#define D_  512
#define H_  128
#define H2_ (H_ / 2)   // 64 half2 per row

// Scratch for projected q and k in fp16: [B*L, H] as half2 pairs
__device__ __half2 g_qh[B_ * LQ_ * H2_];
__device__ __half2 g_kh[B_ * LK_ * H2_];

__device__ __forceinline__ unsigned tanh2_fast(unsigned x) {
    unsigned y;
    asm("tanh.approx.f16x2 %0, %1;" : "=r"(y) : "r"(x));
    return y;
}

// Packed fp32 pair helpers (sm_100+): exact fp32 math, 2 FMA per instruction.
__device__ __forceinline__ void fma2(unsigned long long& d,
                                     unsigned long long a,
                                     unsigned long long b) {
    asm("fma.rn.f32x2 %0, %1, %2, %0;" : "+l"(d) : "l"(a), "l"(b));
}
__device__ __forceinline__ unsigned long long dup_f32(float v) {
    unsigned long long r;
    asm("mov.b64 %0, {%1, %1};" : "=l"(r) : "f"(v));
    return r;
}
__device__ __forceinline__ void unpack_f32x2(float& lo, float& hi,
                                             unsigned long long v) {
    asm("mov.b64 {%0, %1}, %2;" : "=f"(lo), "=f"(hi) : "l"(v));
}

// ---------------------------------------------------------------------------
// Projection GEMM: Y[m, h] = sum_d X[m, d] * W[d, h], output packed fp16.
// M = 4096 (= B*L), K = 512, N = 128.
// CTA tile: 32 x 128, 256 threads, 4x4 outputs per thread, K-chunk 32.
// Inner loop uses fma.rn.f32x2 (FFMA2): A-tile stored pre-duplicated {a,a}
// as 64-bit smem entries (warp-broadcast LDS.64), B row read as ulonglong2.
// blockIdx.y: 0 -> (qs, Wq, g_qh), 1 -> (ks, Wk, g_kh)
// ---------------------------------------------------------------------------
__global__ __launch_bounds__(256) void proj_kernel(
    const float* __restrict__ qs, const float* __restrict__ ks,
    const float* __restrict__ Wq, const float* __restrict__ Wk)
{
    const float* X = blockIdx.y ? ks : qs;
    const float* W = blockIdx.y ? Wk : Wq;
    __half2* Y     = blockIdx.y ? g_kh : g_qh;

    __shared__ unsigned long long As2[32][32];  // 8 KB, each entry = {a, a}
    __shared__ float Bs[32][128];               // 16 KB

    const int tid = threadIdx.x;        // 0..255
    const int tx  = tid & 31;           // n-group: n0 = tx*4
    const int ty  = tid >> 5;           // m-group: m0 = ty*4 (0..7)
    const int m_base = blockIdx.x * 32;

    unsigned long long acc01[4], acc23[4];  // {n0,n1} and {n2,n3} per m-row
#pragma unroll
    for (int i = 0; i < 4; i++) { acc01[i] = 0ull; acc23[i] = 0ull; }

    for (int k0 = 0; k0 < D_; k0 += 32) {
        // Load A tile: 32x32 floats = 256 float4, one per thread; store duplicated.
        {
            int row = tid >> 3;           // 0..31
            int c4  = tid & 7;            // 0..7
            float4 v = *reinterpret_cast<const float4*>(
                &X[(size_t)(m_base + row) * D_ + k0 + c4 * 4]);
            As2[row][c4 * 4 + 0] = dup_f32(v.x);
            As2[row][c4 * 4 + 1] = dup_f32(v.y);
            As2[row][c4 * 4 + 2] = dup_f32(v.z);
            As2[row][c4 * 4 + 3] = dup_f32(v.w);
        }
        // Load B tile: 32x128 floats = 1024 float4, four per thread.
#pragma unroll
        for (int l = 0; l < 4; l++) {
            int idx = l * 256 + tid;      // 0..1023
            int row = idx >> 5;           // 0..31
            int c4  = idx & 31;           // 0..31
            float4 v = *reinterpret_cast<const float4*>(
                &W[(size_t)(k0 + row) * H_ + c4 * 4]);
            *reinterpret_cast<float4*>(&Bs[row][c4 * 4]) = v;
        }
        __syncthreads();

#pragma unroll
        for (int kk = 0; kk < 32; kk++) {
            ulonglong2 b = *reinterpret_cast<const ulonglong2*>(&Bs[kk][tx * 4]);
#pragma unroll
            for (int i = 0; i < 4; i++) {
                unsigned long long a2 = As2[ty * 4 + i][kk];  // broadcast
                fma2(acc01[i], a2, b.x);
                fma2(acc23[i], a2, b.y);
            }
        }
        __syncthreads();
    }

    // Store 4x4 per thread as 2 half2 (= uint2) per row.
#pragma unroll
    for (int i = 0; i < 4; i++) {
        float n0, n1, n2, n3;
        unpack_f32x2(n0, n1, acc01[i]);
        unpack_f32x2(n2, n3, acc23[i]);
        __half2 h0 = __floats2half2_rn(n0, n1);
        __half2 h1 = __floats2half2_rn(n2, n3);
        uint2 u;
        u.x = *reinterpret_cast<unsigned*>(&h0);
        u.y = *reinterpret_cast<unsigned*>(&h1);
        *reinterpret_cast<uint2*>(
            &Y[(size_t)(m_base + ty * 4 + i) * H2_ + tx * 2]) = u;
    }
}

// ---------------------------------------------------------------------------
// Scoring kernel: out[b,i,j] = sum_h wv[h] * tanh(q[b,i,h] + k[b,j,h])
// q,k in fp16 (half2); tanh.approx.f16x2 does 2 h-values per MUFU op.
// Accumulation in fp32. CTA tile 64 x 64, 256 threads, 4x4 per thread.
// Smem tiles: [64][68] half2 (stride 68 words -> conflict-free LDS.128).
// ---------------------------------------------------------------------------
#define TSTRIDE2 68   // half2 units per row (68 mod 32 == 4)
#define SCORE_SMEM_BYTES (2 * 64 * TSTRIDE2 * 4 + H_ * 4)

__global__ __launch_bounds__(256, 3) void score_kernel(
    const float* __restrict__ wv, float* __restrict__ out)
{
    extern __shared__ char smem_raw[];
    __half2* Qs = reinterpret_cast<__half2*>(smem_raw);                  // [64][68]
    __half2* Ks = Qs + 64 * TSTRIDE2;                                    // [64][68]
    float*  sWv = reinterpret_cast<float*>(smem_raw + 2 * 64 * TSTRIDE2 * 4); // [128]

    const int tid = threadIdx.x;          // 0..255
    const int tx  = tid & 15;             // j-lane: j = jj*16 + tx
    const int ty  = tid >> 4;             // i-group: i0 = ty*4 (0..15)

    const int jt = blockIdx.x;            // j tile (0..7)
    const int it = blockIdx.y;            // i tile (0..7)
    const int b  = blockIdx.z;            // batch

    const __half2* qsrc = &g_qh[((size_t)b * LQ_ + it * 64) * H2_];
    const __half2* ksrc = &g_kh[((size_t)b * LK_ + jt * 64) * H2_];

    // Load Q and K tiles: 64 rows x 64 half2 = 1024 float4 per tile.
#pragma unroll
    for (int l = 0; l < 4; l++) {
        int idx = l * 256 + tid;          // 0..1023
        int row = idx >> 4;               // 0..63
        int c4  = idx & 15;               // 0..15
        float4 q = *reinterpret_cast<const float4*>(&qsrc[(size_t)row * H2_ + c4 * 4]);
        float4 k = *reinterpret_cast<const float4*>(&ksrc[(size_t)row * H2_ + c4 * 4]);
        *reinterpret_cast<float4*>(&Qs[row * TSTRIDE2 + c4 * 4]) = q;
        *reinterpret_cast<float4*>(&Ks[row * TSTRIDE2 + c4 * 4]) = k;
    }
    if (tid < H_) sWv[tid] = wv[tid];
    __syncthreads();

    float acc[4][4];
#pragma unroll
    for (int i = 0; i < 4; i++)
#pragma unroll
        for (int j = 0; j < 4; j++) acc[i][j] = 0.0f;

#pragma unroll 2
    for (int h2 = 0; h2 < H2_; h2 += 4) {   // 8 h-values per iter
        float4 wva = *reinterpret_cast<const float4*>(&sWv[h2 * 2]);
        float4 wvb = *reinterpret_cast<const float4*>(&sWv[h2 * 2 + 4]);
        float wvf[8] = {wva.x, wva.y, wva.z, wva.w, wvb.x, wvb.y, wvb.z, wvb.w};

        __half2 q2[4][4], k2[4][4];
#pragma unroll
        for (int ii = 0; ii < 4; ii++)
            *reinterpret_cast<float4*>(q2[ii]) =
                *reinterpret_cast<const float4*>(&Qs[(ty * 4 + ii) * TSTRIDE2 + h2]);
#pragma unroll
        for (int jj = 0; jj < 4; jj++)
            *reinterpret_cast<float4*>(k2[jj]) =
                *reinterpret_cast<const float4*>(&Ks[(jj * 16 + tx) * TSTRIDE2 + h2]);

#pragma unroll
        for (int ii = 0; ii < 4; ii++) {
#pragma unroll
            for (int jj = 0; jj < 4; jj++) {
                float a = acc[ii][jj];
#pragma unroll
                for (int p = 0; p < 4; p++) {
                    __half2 s = __hadd2(q2[ii][p], k2[jj][p]);
                    unsigned t = tanh2_fast(*reinterpret_cast<unsigned*>(&s));
                    float2 tf = __half22float2(*reinterpret_cast<__half2*>(&t));
                    a = fmaf(wvf[2 * p],     tf.x, a);
                    a = fmaf(wvf[2 * p + 1], tf.y, a);
                }
                acc[ii][jj] = a;
            }
        }
    }

    // Write out: out[b][it*64 + ty*4+ii][jt*64 + jj*16+tx]
    float* obase = &out[((size_t)b * LQ_ + it * 64 + ty * 4) * LK_ + jt * 64];
#pragma unroll
    for (int ii = 0; ii < 4; ii++) {
#pragma unroll
        for (int jj = 0; jj < 4; jj++) {
            obase[(size_t)ii * LK_ + jj * 16 + tx] = acc[ii][jj];
        }
    }
}

// ---------------------------------------------------------------------------
extern "C" void kernel_launch(void* const* d_in, const int* in_sizes, int n_in,
                              void* d_out, int out_size)
{
    const float* qs = (const float*)d_in[0];
    const float* ks = (const float*)d_in[1];
    const float* Wq = (const float*)d_in[2];
    const float* Wk = (const float*)d_in[3];
    const float* wv = (const float*)d_in[4];
    float* out = (float*)d_out;

    cudaFuncSetAttribute(score_kernel,
                         cudaFuncAttributeMaxDynamicSharedMemorySize,
                         SCORE_SMEM_BYTES);

    // Projections: grid (M/32, 2) = (128, 2)
    proj_kernel<<<dim3(128, 2), 256>>>(qs, ks, Wq, Wk);

    // Scoring: grid (LK/64, LQ/64, B) = (8, 8, 8)
    score_kernel<<<dim3(LK_ / 64, LQ_ / 64, B_), 256, SCORE_SMEM_BYTES>>>(wv, out);
}

// round 14
// speedup vs baseline: 1.0141x; 1.0141x over previous
#include <cuda_runtime.h>
#include <cuda_fp16.h>
#include <cstdint>

// Problem dims
#define B_  8
#define LQ_ 512
#define LK_ 512
#define D_  512
#define H_  128
#define H2_ (H_ / 2)   // 64 half2 per row

// Scratch for projected q and k in fp16: [B*L, H] as half2 pairs
__device__ __half2 g_qh[B_ * LQ_ * H2_];
__device__ __half2 g_kh[B_ * LK_ * H2_];

__device__ __forceinline__ __half2 tanh2_fast(__half2 x) {
    unsigned y, xi = *reinterpret_cast<unsigned*>(&x);
    asm("tanh.approx.f16x2 %0, %1;" : "=r"(y) : "r"(xi));
    return *reinterpret_cast<__half2*>(&y);
}

// ---------------------------------------------------------------------------
// Projection GEMM (R3-measured fp32 inner loop, fp16 epilogue):
// Y[m, h] = sum_d X[m, d] * W[d, h].  M = 4096, K = 512, N = 128.
// CTA tile: 32 x 128, 256 threads, 4x4 outputs per thread, K-chunk 32.
// blockIdx.y: 0 -> (qs, Wq, g_qh), 1 -> (ks, Wk, g_kh)
// ---------------------------------------------------------------------------
__global__ __launch_bounds__(256) void proj_kernel(
    const float* __restrict__ qs, const float* __restrict__ ks,
    const float* __restrict__ Wq, const float* __restrict__ Wk)
{
    const float* X = blockIdx.y ? ks : qs;
    const float* W = blockIdx.y ? Wk : Wq;
    __half2* Y     = blockIdx.y ? g_kh : g_qh;

    __shared__ float As[32][32];    // 4 KB
    __shared__ float Bs[32][128];   // 16 KB

    const int tid = threadIdx.x;        // 0..255
    const int tx  = tid & 31;           // n-group: n0 = tx*4
    const int ty  = tid >> 5;           // m-group: m0 = ty*4 (0..7)
    const int m_base = blockIdx.x * 32;

    float acc[4][4];
#pragma unroll
    for (int i = 0; i < 4; i++)
#pragma unroll
        for (int j = 0; j < 4; j++) acc[i][j] = 0.0f;

    for (int k0 = 0; k0 < D_; k0 += 32) {
        // Load A tile: 32x32 floats = 256 float4, one per thread.
        {
            int row = tid >> 3;           // 0..31
            int c4  = tid & 7;            // 0..7
            float4 v = *reinterpret_cast<const float4*>(
                &X[(size_t)(m_base + row) * D_ + k0 + c4 * 4]);
            *reinterpret_cast<float4*>(&As[row][c4 * 4]) = v;
        }
        // Load B tile: 32x128 floats = 1024 float4, four per thread.
#pragma unroll
        for (int l = 0; l < 4; l++) {
            int idx = l * 256 + tid;      // 0..1023
            int row = idx >> 5;           // 0..31
            int c4  = idx & 31;           // 0..31
            float4 v = *reinterpret_cast<const float4*>(
                &W[(size_t)(k0 + row) * H_ + c4 * 4]);
            *reinterpret_cast<float4*>(&Bs[row][c4 * 4]) = v;
        }
        __syncthreads();

#pragma unroll
        for (int kk = 0; kk < 32; kk++) {
            float4 b = *reinterpret_cast<const float4*>(&Bs[kk][tx * 4]);
            float a0 = As[ty * 4 + 0][kk];
            float a1 = As[ty * 4 + 1][kk];
            float a2 = As[ty * 4 + 2][kk];
            float a3 = As[ty * 4 + 3][kk];
            acc[0][0] += a0 * b.x; acc[0][1] += a0 * b.y; acc[0][2] += a0 * b.z; acc[0][3] += a0 * b.w;
            acc[1][0] += a1 * b.x; acc[1][1] += a1 * b.y; acc[1][2] += a1 * b.z; acc[1][3] += a1 * b.w;
            acc[2][0] += a2 * b.x; acc[2][1] += a2 * b.y; acc[2][2] += a2 * b.z; acc[2][3] += a2 * b.w;
            acc[3][0] += a3 * b.x; acc[3][1] += a3 * b.y; acc[3][2] += a3 * b.z; acc[3][3] += a3 * b.w;
        }
        __syncthreads();
    }

    // Store 4x4 per thread as 2 half2 (= uint2) per row.
#pragma unroll
    for (int i = 0; i < 4; i++) {
        __half2 h0 = __floats2half2_rn(acc[i][0], acc[i][1]);
        __half2 h1 = __floats2half2_rn(acc[i][2], acc[i][3]);
        uint2 u;
        u.x = *reinterpret_cast<unsigned*>(&h0);
        u.y = *reinterpret_cast<unsigned*>(&h1);
        *reinterpret_cast<uint2*>(
            &Y[(size_t)(m_base + ty * 4 + i) * H2_ + tx * 2]) = u;
    }
}

// ---------------------------------------------------------------------------
// Scoring kernel: out[b,i,j] = sum_h wv[h] * tanh(q[b,i,h] + k[b,j,h])
// fp16 q/k; tanh.approx.f16x2. Per 8-h group: products+partial sum in fp16
// via HFMA2 (fma pipe), ONE half2->float2 conversion per group (2 F2F on XU
// instead of 8), fp32 master accumulator. XU cost/8h: 4 MUFU + 2 F2F.
// CTA tile 64 x 64, 256 threads, 4x4 per thread.
// ---------------------------------------------------------------------------
#define TSTRIDE2 68   // half2 units per row (68 mod 32 == 4) -> conflict-free
#define SCORE_SMEM_BYTES (2 * 64 * TSTRIDE2 * 4 + H2_ * 4)

__global__ __launch_bounds__(256, 3) void score_kernel(
    const float* __restrict__ wv, float* __restrict__ out)
{
    extern __shared__ char smem_raw[];
    __half2* Qs   = reinterpret_cast<__half2*>(smem_raw);                    // [64][68]
    __half2* Ks   = Qs + 64 * TSTRIDE2;                                      // [64][68]
    __half2* sWv2 = reinterpret_cast<__half2*>(smem_raw + 2 * 64 * TSTRIDE2 * 4); // [64]

    const int tid = threadIdx.x;          // 0..255
    const int tx  = tid & 15;             // j-lane: j = jj*16 + tx
    const int ty  = tid >> 4;             // i-group: i0 = ty*4 (0..15)

    const int jt = blockIdx.x;            // j tile (0..7)
    const int it = blockIdx.y;            // i tile (0..7)
    const int b  = blockIdx.z;            // batch

    const __half2* qsrc = &g_qh[((size_t)b * LQ_ + it * 64) * H2_];
    const __half2* ksrc = &g_kh[((size_t)b * LK_ + jt * 64) * H2_];

    // Load Q and K tiles: 64 rows x 64 half2 = 1024 float4 per tile.
#pragma unroll
    for (int l = 0; l < 4; l++) {
        int idx = l * 256 + tid;          // 0..1023
        int row = idx >> 4;               // 0..63
        int c4  = idx & 15;               // 0..15
        float4 q = *reinterpret_cast<const float4*>(&qsrc[(size_t)row * H2_ + c4 * 4]);
        float4 k = *reinterpret_cast<const float4*>(&ksrc[(size_t)row * H2_ + c4 * 4]);
        *reinterpret_cast<float4*>(&Qs[row * TSTRIDE2 + c4 * 4]) = q;
        *reinterpret_cast<float4*>(&Ks[row * TSTRIDE2 + c4 * 4]) = k;
    }
    if (tid < H2_) {
        float2 w = *reinterpret_cast<const float2*>(&wv[tid * 2]);
        sWv2[tid] = __floats2half2_rn(w.x, w.y);
    }
    __syncthreads();

    float acc[4][4];
#pragma unroll
    for (int i = 0; i < 4; i++)
#pragma unroll
        for (int j = 0; j < 4; j++) acc[i][j] = 0.0f;

#pragma unroll 2
    for (int h2 = 0; h2 < H2_; h2 += 4) {   // one group = 4 half2 = 8 h-values
        __half2 w2[4];
        *reinterpret_cast<float4*>(w2) =
            *reinterpret_cast<const float4*>(&sWv2[h2]);

        __half2 q2[4][4], k2[4][4];
#pragma unroll
        for (int ii = 0; ii < 4; ii++)
            *reinterpret_cast<float4*>(q2[ii]) =
                *reinterpret_cast<const float4*>(&Qs[(ty * 4 + ii) * TSTRIDE2 + h2]);
#pragma unroll
        for (int jj = 0; jj < 4; jj++)
            *reinterpret_cast<float4*>(k2[jj]) =
                *reinterpret_cast<const float4*>(&Ks[(jj * 16 + tx) * TSTRIDE2 + h2]);

#pragma unroll
        for (int ii = 0; ii < 4; ii++) {
#pragma unroll
            for (int jj = 0; jj < 4; jj++) {
                __half2 ps = __floats2half2_rn(0.0f, 0.0f);
#pragma unroll
                for (int p = 0; p < 4; p++) {
                    __half2 t = tanh2_fast(__hadd2(q2[ii][p], k2[jj][p]));
                    ps = __hfma2(w2[p], t, ps);
                }
                float2 pf = __half22float2(ps);   // single 2xF2F per group
                acc[ii][jj] += pf.x + pf.y;
            }
        }
    }

    // Write out: out[b][it*64 + ty*4+ii][jt*64 + jj*16+tx]
    float* obase = &out[((size_t)b * LQ_ + it * 64 + ty * 4) * LK_ + jt * 64];
#pragma unroll
    for (int ii = 0; ii < 4; ii++) {
#pragma unroll
        for (int jj = 0; jj < 4; jj++) {
            obase[(size_t)ii * LK_ + jj * 16 + tx] = acc[ii][jj];
        }
    }
}

// ---------------------------------------------------------------------------
extern "C" void kernel_launch(void* const* d_in, const int* in_sizes, int n_in,
                              void* d_out, int out_size)
{
    const float* qs = (const float*)d_in[0];
    const float* ks = (const float*)d_in[1];
    const float* Wq = (const float*)d_in[2];
    const float* Wk = (const float*)d_in[3];
    const float* wv = (const float*)d_in[4];
    float* out = (float*)d_out;

    cudaFuncSetAttribute(score_kernel,
                         cudaFuncAttributeMaxDynamicSharedMemorySize,
                         SCORE_SMEM_BYTES);

    // Projections: grid (M/32, 2) = (128, 2)
    proj_kernel<<<dim3(128, 2), 256>>>(qs, ks, Wq, Wk);

    // Scoring: grid (LK/64, LQ/64, B) = (8, 8, 8)
    score_kernel<<<dim3(LK_ / 64, LQ_ / 64, B_), 256, SCORE_SMEM_BYTES>>>(wv, out);
}